// round 16
// baseline (speedup 1.0000x reference)
#include <cuda_runtime.h>
#include <cuda_fp16.h>
#include <stdint.h>

#define N_BCH 8
#define N_ATM 10000
#define N_ELM 100
#define THREADS 640
#define NWARP  20
#define GRID_MAIN 148            // 1 CTA per SM
#define STAGES 4                 // 4 half-stages, 3-deep lookahead

#define ELM_BYTES  (N_BCH * N_ATM)              // 80000
#define PAIR_N     (N_ELM * N_ELM)              // 10000
#define ARR_B      (THREADS * 8)                // 5120 per array per stage
#define STG_B      (4 * ARR_B)                  // 20480 per stage
// smem layout (bytes)
#define SMEM_MBAR  0                            // full[4] @0, empty[4] @32
#define SMEM_ACC   128                          // 8*640 floats = 20480
#define SMEM_PAIR  (128 + 20480)                // 40000
#define SMEM_ELM   (SMEM_PAIR + 40000)          // 80000
#define SMEM_BUF   (SMEM_ELM + ELM_BYTES)       // 140608 (16B aligned)
#define SMEM_TOTAL (SMEM_BUF + STAGES * STG_B)  // 222528

__device__ uint8_t g_elm8[ELM_BYTES];

__device__ __forceinline__ float fsqrt_approx(float x)
{
    float y;
    asm("sqrt.approx.f32 %0, %1;" : "=f"(y) : "f"(x));
    return y;
}

__device__ __forceinline__ uint32_t smem_u32(const void* p)
{
    uint32_t a;
    asm("{ .reg .u64 t; cvta.to.shared.u64 t, %1; cvt.u32.u64 %0, t; }"
        : "=r"(a) : "l"(p));
    return a;
}

__device__ __forceinline__ void mbar_init(uint32_t mbar, uint32_t count)
{
    asm volatile("mbarrier.init.shared.b64 [%0], %1;"
                 :: "r"(mbar), "r"(count) : "memory");
}
__device__ __forceinline__ void mbar_expect_tx(uint32_t mbar, uint32_t bytes)
{
    asm volatile("mbarrier.arrive.expect_tx.shared.b64 _, [%0], %1;"
                 :: "r"(mbar), "r"(bytes) : "memory");
}
__device__ __forceinline__ void mbar_arrive(uint32_t mbar)
{
    asm volatile("mbarrier.arrive.shared.b64 _, [%0];"
                 :: "r"(mbar) : "memory");
}
__device__ __forceinline__ void mbar_wait(uint32_t mbar, uint32_t parity)
{
    uint32_t done;
    asm volatile(
        "{\n\t.reg .pred p;\n\t"
        "mbarrier.try_wait.parity.acquire.cta.shared::cta.b64 p, [%1], %2;\n\t"
        "selp.b32 %0, 1, 0, p;\n\t}"
        : "=r"(done) : "r"(mbar), "r"(parity) : "memory");
    if (!done) {
        asm volatile(
            "{\n\t.reg .pred P1;\n\t"
            "WAIT_LOOP_%=:\n\t"
            "mbarrier.try_wait.parity.acquire.cta.shared::cta.b64 P1, [%0], %1, 0x989680;\n\t"
            "@P1 bra.uni WAIT_DONE_%=;\n\t"
            "bra.uni WAIT_LOOP_%=;\n\t"
            "WAIT_DONE_%=:\n\t}"
            :: "r"(mbar), "r"(parity) : "memory");
    }
}
__device__ __forceinline__ void bulk_g2s(uint32_t dst, const void* src,
                                         uint32_t bytes, uint32_t mbar)
{
    asm volatile(
        "cp.async.bulk.shared::cta.global.mbarrier::complete_tx::bytes "
        "[%0], [%1], %2, [%3];"
        :: "r"(dst), "l"(src), "r"(bytes), "r"(mbar) : "memory");
}

// ---------------------------------------------------------------------------
// Prepass: zero outputs, convert elm int32 -> uint8 (values < 100).
// ---------------------------------------------------------------------------
__global__ void prep_kernel(const int* __restrict__ elm, float* __restrict__ out)
{
    int tid = blockIdx.x * blockDim.x + threadIdx.x;
    if (tid < N_BCH) out[tid] = 0.0f;
    for (int i = tid; i < ELM_BYTES; i += gridDim.x * blockDim.x)
        g_elm8[i] = (uint8_t)elm[i];
}

// ---------------------------------------------------------------------------
// Per-edge work: 2 u8 elm gathers + 1 half2 pair gather + smem RMW.
// ---------------------------------------------------------------------------
__device__ __forceinline__ void edge_op(int n, int i, int j, float s,
                                        const uint8_t* __restrict__ elm_s,
                                        const __half2* __restrict__ pair,
                                        float* __restrict__ acc_base)
{
    int nb = n * N_ATM;
    int ea = elm_s[nb + i];
    int eb = elm_s[nb + j];
    __half2 h = pair[ea * N_ELM + eb];
    float kk = __low2float(h);
    float R  = __high2float(h);
    float dis = fsqrt_approx(s);
    if (dis < R) {
        float d = dis - R;
        acc_base[n << 5] += kk * d * d;
    }
}

__global__ void __launch_bounds__(THREADS, 1)
close_penalty_kernel(const int2*  __restrict__ edge_n2,
                     const int2*  __restrict__ edge_i2,
                     const int2*  __restrict__ edge_j2,
                     const float2* __restrict__ sod2,
                     const int*   __restrict__ edge_n,
                     const int*   __restrict__ edge_i,
                     const int*   __restrict__ edge_j,
                     const float* __restrict__ sod,
                     const float* __restrict__ k,
                     const float* __restrict__ radius,
                     float* __restrict__ out,
                     int nvec2, int E)
{
    extern __shared__ char smem[];
    float*   acc   = (float*)  (smem + SMEM_ACC);
    __half2* pair  = (__half2*)(smem + SMEM_PAIR);
    uint8_t* elm_s = (uint8_t*)(smem + SMEM_ELM);
    char*    buf   = smem + SMEM_BUF;

    int tid  = threadIdx.x;
    int lane = tid & 31;
    int wid  = tid >> 5;

    uint32_t mb_base = smem_u32(smem + SMEM_MBAR);
    uint32_t full_mb[STAGES], empty_mb[STAGES];
    #pragma unroll
    for (int s = 0; s < STAGES; s++) {
        full_mb[s]  = mb_base + s * 8;
        empty_mb[s] = mb_base + 32 + s * 8;
    }
    if (tid == 0) {
        #pragma unroll
        for (int s = 0; s < STAGES; s++) {
            mbar_init(full_mb[s], 1);        // expect_tx arrival + tx bytes
            mbar_init(empty_mb[s], NWARP);   // lane0-per-warp arrivals
        }
    }

    #pragma unroll
    for (int b = 0; b < 8; b++) acc[b * THREADS + tid] = 0.0f;

    // Build fused (kk, R) half2 pair table: 10000 entries.
    for (int idx = tid; idx < PAIR_N; idx += THREADS) {
        int a = idx / N_ELM;
        int b = idx - a * N_ELM;
        float kk = __ldg(&k[a]) + __ldg(&k[b]);
        float R  = __ldg(&radius[a]) + __ldg(&radius[b]);
        pair[idx] = __floats2half2_rn(kk, R);
    }

    // Copy 80 KB u8 element table into shared memory (16B chunks).
    {
        const int4* src = (const int4*)g_elm8;
        int4*       dst = (int4*)(smem + SMEM_ELM);
        for (int i = tid; i < ELM_BYTES / 16; i += THREADS)
            dst[i] = __ldg(&src[i]);
    }
    __syncthreads();   // mbarriers + tables ready

    float* acc_base = &acc[(wid << 8) | lane];   // + (n<<5) per edge

    uint32_t buf_s = smem_u32(buf);
    int nblk = (nvec2 + THREADS - 1) / THREADS;  // blocks of 640 int2 groups

    // Producer fill: one thread issues 4 bulk copies + expect_tx.
    auto fill = [&](int blk, int s) {
        long base  = (long)blk * THREADS;
        long remn  = nvec2 - base;
        uint32_t n = remn >= THREADS ? THREADS : (uint32_t)remn;
        uint32_t bytes = n * 8;
        bytes = (bytes + 15) & ~15u;             // bulk size multiple of 16
        uint32_t so = buf_s + (uint32_t)s * STG_B;
        mbar_expect_tx(full_mb[s], 4 * bytes);
        bulk_g2s(so + 0 * ARR_B, &edge_n2[base], bytes, full_mb[s]);
        bulk_g2s(so + 1 * ARR_B, &edge_i2[base], bytes, full_mb[s]);
        bulk_g2s(so + 2 * ARR_B, &edge_j2[base], bytes, full_mb[s]);
        bulk_g2s(so + 3 * ARR_B, &sod2[base],    bytes, full_mb[s]);
    };

    // Prologue: fill up to STAGES-1 stages ahead.
    if (tid == 0) {
        #pragma unroll
        for (int p = 0; p < STAGES - 1; p++) {
            int blk = blockIdx.x + p * gridDim.x;
            if (blk < nblk) fill(blk, p);
        }
    }

    uint32_t f_ph[STAGES] = {0, 0, 0, 0};
    uint32_t e_ph[STAGES] = {0, 0, 0, 0};

    for (int it = 0; ; it++) {
        int blk_cons = blockIdx.x + it * gridDim.x;
        if (blk_cons >= nblk) break;
        int s = it & (STAGES - 1);

        mbar_wait(full_mb[s], f_ph[s]);
        f_ph[s] ^= 1;

        long base = (long)blk_cons * THREADS + tid;
        if (base < nvec2) {
            const char* sp = buf + (size_t)s * STG_B + (size_t)tid * 8;
            int2   en = *(const int2*)  (sp + 0 * ARR_B);
            int2   ei = *(const int2*)  (sp + 1 * ARR_B);
            int2   ej = *(const int2*)  (sp + 2 * ARR_B);
            float2 sd = *(const float2*)(sp + 3 * ARR_B);

            edge_op(en.x, ei.x, ej.x, sd.x, elm_s, pair, acc_base);
            edge_op(en.y, ei.y, ej.y, sd.y, elm_s, pair, acc_base);
        }

        __syncwarp();
        if (lane == 0) mbar_arrive(empty_mb[s]);

        if (tid == 0) {
            int jt = it + STAGES - 1;
            int blk_f = blockIdx.x + jt * gridDim.x;
            if (blk_f < nblk) {
                int sf = jt & (STAGES - 1);
                if (jt >= STAGES) {          // stage reused: wait prior drain
                    mbar_wait(empty_mb[sf], e_ph[sf]);
                    e_ph[sf] ^= 1;
                }
                fill(blk_f, sf);
            }
        }
    }

    // Scalar tail (E odd)
    int gtid = blockIdx.x * THREADS + tid;
    int t = nvec2 * 2 + gtid;
    if (t < E)
        edge_op(edge_n[t], edge_i[t], edge_j[t], sod[t], elm_s, pair, acc_base);

    __syncthreads();

    // Reduce: first 256 threads; thread owns (bin = tid>>5, lane).
    if (tid < 256) {
        int bin = tid >> 5;
        float sum = 0.0f;
        #pragma unroll
        for (int w = 0; w < NWARP; w++)
            sum += acc[(w << 8) + (bin << 5) + lane];
        #pragma unroll
        for (int off = 16; off > 0; off >>= 1)
            sum += __shfl_down_sync(0xFFFFFFFFu, sum, off);
        if (lane == 0)
            atomicAdd(&out[bin], sum);
    }
}

// ---------------------------------------------------------------------------
// Launch
// ---------------------------------------------------------------------------
extern "C" void kernel_launch(void* const* d_in, const int* in_sizes, int n_in,
                              void* d_out, int out_size)
{
    const int*   elm    = (const int*)  d_in[0];
    const int*   edge_n = (const int*)  d_in[1];
    const int*   edge_i = (const int*)  d_in[2];
    const int*   edge_j = (const int*)  d_in[3];
    const float* sod    = (const float*)d_in[4];
    const float* k      = (const float*)d_in[5];
    const float* radius = (const float*)d_in[6];
    float* out = (float*)d_out;

    int E     = in_sizes[1];
    int nvec2 = E >> 1;

    cudaFuncSetAttribute(close_penalty_kernel,
                         cudaFuncAttributeMaxDynamicSharedMemorySize, SMEM_TOTAL);

    prep_kernel<<<(ELM_BYTES + 255) / 256, 256>>>(elm, out);

    int grid = GRID_MAIN;
    int nblk = (nvec2 + THREADS - 1) / THREADS;
    if (nblk < grid) grid = nblk > 0 ? nblk : 1;

    close_penalty_kernel<<<grid, THREADS, SMEM_TOTAL>>>(
        (const int2*)edge_n, (const int2*)edge_i, (const int2*)edge_j,
        (const float2*)sod,
        edge_n, edge_i, edge_j, sod,
        k, radius,
        out, nvec2, E);
}

// round 17
// speedup vs baseline: 2.0611x; 2.0611x over previous
#include <cuda_runtime.h>
#include <cuda_fp16.h>
#include <stdint.h>

#define N_BCH 8
#define N_ATM 10000
#define N_ELM 100
#define THREADS 768
#define NWARP  24
#define GRID_MAIN 148            // 1 CTA per SM
#define STAGES 2

#define ELM_BYTES  (N_BCH * N_ATM)              // 80000
#define PAIR_N     (N_ELM * N_ELM)              // 10000
// smem layout (bytes)
#define SMEM_PAIR  0                            // 10000 half2 = 40000
#define SMEM_ELM   40000                        // 80000
#define SMEM_BUF   (SMEM_ELM + ELM_BYTES)       // 120000 (16B aligned)
#define ARR_B      (THREADS * 16)               // 12288
#define STG_B      (4 * ARR_B)                  // 49152
#define SMEM_TOTAL (SMEM_BUF + STAGES * STG_B)  // 218304

__device__ uint8_t g_elm8[ELM_BYTES];

__device__ __forceinline__ float fsqrt_approx(float x)
{
    float y;
    asm("sqrt.approx.f32 %0, %1;" : "=f"(y) : "f"(x));
    return y;
}

__device__ __forceinline__ void cp16(uint32_t saddr, const void* gptr)
{
    asm volatile("cp.async.cg.shared.global [%0], [%1], 16;\n"
                 :: "r"(saddr), "l"(gptr));
}
__device__ __forceinline__ void cp_commit()
{
    asm volatile("cp.async.commit_group;\n");
}
template <int N>
__device__ __forceinline__ void cp_wait()
{
    asm volatile("cp.async.wait_group %0;\n" :: "n"(N));
}

__device__ __forceinline__ uint32_t smem_u32(const void* p)
{
    uint32_t a;
    asm("{ .reg .u64 t; cvta.to.shared.u64 t, %1; cvt.u32.u64 %0, t; }"
        : "=r"(a) : "l"(p));
    return a;
}

// ---------------------------------------------------------------------------
// Prepass: zero outputs, convert elm int32 -> uint8 (values < 100).
// ---------------------------------------------------------------------------
__global__ void prep_kernel(const int* __restrict__ elm, float* __restrict__ out)
{
    int tid = blockIdx.x * blockDim.x + threadIdx.x;
    if (tid < N_BCH) out[tid] = 0.0f;
    for (int i = tid; i < ELM_BYTES; i += gridDim.x * blockDim.x)
        g_elm8[i] = (uint8_t)elm[i];
}

// ---------------------------------------------------------------------------
// Per-edge work: 2 u8 elm gathers + 1 half2 pair gather + REGISTER bin adds.
// (No smem RMW: trades 2 LSU ops/edge for ~15 ALU ops on idle pipes.)
// ---------------------------------------------------------------------------
__device__ __forceinline__ void edge_op(int n, int i, int j, float s,
                                        const uint8_t* __restrict__ elm_s,
                                        const __half2* __restrict__ pair,
                                        float* __restrict__ a)   // a[8] regs
{
    int nb = n * N_ATM;
    int ea = elm_s[nb + i];
    int eb = elm_s[nb + j];
    __half2 h = pair[ea * N_ELM + eb];
    float kk = __low2float(h);
    float R  = __high2float(h);
    float dis = fsqrt_approx(s);
    float d   = dis - R;
    float v   = (dis < R) ? kk * d * d : 0.0f;

    // two-level predicated bin select: n = 4*(n>>2) + (n&3)
    float vlo = (n & 4) ? 0.0f : v;
    float vhi = (n & 4) ? v    : 0.0f;
    int   m   = n & 3;
    #pragma unroll
    for (int c = 0; c < 4; c++) {
        bool p = (m == c);
        a[c]     += p ? vlo : 0.0f;
        a[c + 4] += p ? vhi : 0.0f;
    }
}

__global__ void __launch_bounds__(THREADS, 1)
close_penalty_kernel(const int4*  __restrict__ edge_n4,
                     const int4*  __restrict__ edge_i4,
                     const int4*  __restrict__ edge_j4,
                     const float4* __restrict__ sod4,
                     const int*   __restrict__ edge_n,
                     const int*   __restrict__ edge_i,
                     const int*   __restrict__ edge_j,
                     const float* __restrict__ sod,
                     const float* __restrict__ k,
                     const float* __restrict__ radius,
                     float* __restrict__ out,
                     int nvec, int E)
{
    extern __shared__ char smem[];
    __half2* pair  = (__half2*)(smem + SMEM_PAIR);
    uint8_t* elm_s = (uint8_t*)(smem + SMEM_ELM);
    char*    buf   = smem + SMEM_BUF;

    int tid  = threadIdx.x;
    int lane = tid & 31;

    // Build fused (kk, R) half2 pair table: 10000 entries.
    for (int idx = tid; idx < PAIR_N; idx += THREADS) {
        int a = idx / N_ELM;
        int b = idx - a * N_ELM;
        float kk = __ldg(&k[a]) + __ldg(&k[b]);
        float R  = __ldg(&radius[a]) + __ldg(&radius[b]);
        pair[idx] = __floats2half2_rn(kk, R);
    }

    // Copy 80 KB u8 element table into shared memory (16B chunks).
    {
        const int4* src = (const int4*)g_elm8;
        int4*       dst = (int4*)(smem + SMEM_ELM);
        for (int i = tid; i < ELM_BYTES / 16; i += THREADS)
            dst[i] = __ldg(&src[i]);
    }
    __syncthreads();

    float a[8];
    #pragma unroll
    for (int b = 0; b < 8; b++) a[b] = 0.0f;

    uint32_t my_slot = smem_u32(buf) + (uint32_t)tid * 16;

    int nblk = (nvec + THREADS - 1) / THREADS;   // blocks of 768 vec4 groups

    auto stage = [&](int blk, int s) {
        long base = (long)blk * THREADS + tid;
        if (blk < nblk && base < nvec) {
            uint32_t so = my_slot + (uint32_t)s * STG_B;
            cp16(so + 0 * ARR_B, &edge_n4[base]);
            cp16(so + 1 * ARR_B, &edge_i4[base]);
            cp16(so + 2 * ARR_B, &edge_j4[base]);
            cp16(so + 3 * ARR_B, &sod4[base]);
        }
    };

    // Prologue: fill first stage.
    stage(blockIdx.x, 0);
    cp_commit();

    // Main pipelined loop: prefetch it+1 while consuming it.
    for (int it = 0; ; it++) {
        int blk_cons = blockIdx.x + it * gridDim.x;
        if (blk_cons >= nblk) break;

        stage(blockIdx.x + (it + 1) * gridDim.x, (it + 1) % STAGES);
        cp_commit();
        cp_wait<1>();   // our stage's group is complete

        long base = (long)blk_cons * THREADS + tid;
        if (base < nvec) {
            int s = it % STAGES;
            const char* sp = buf + (size_t)s * STG_B + (size_t)tid * 16;
            int4   en = *(const int4*)  (sp + 0 * ARR_B);
            int4   ei = *(const int4*)  (sp + 1 * ARR_B);
            int4   ej = *(const int4*)  (sp + 2 * ARR_B);
            float4 sd = *(const float4*)(sp + 3 * ARR_B);

            edge_op(en.x, ei.x, ej.x, sd.x, elm_s, pair, a);
            edge_op(en.y, ei.y, ej.y, sd.y, elm_s, pair, a);
            edge_op(en.z, ei.z, ej.z, sd.z, elm_s, pair, a);
            edge_op(en.w, ei.w, ej.w, sd.w, elm_s, pair, a);
        }
    }
    cp_wait<0>();

    // Scalar tail
    int gtid = blockIdx.x * THREADS + tid;
    int t = nvec * 4 + gtid;
    if (t < E)
        edge_op(edge_n[t], edge_i[t], edge_j[t], sod[t], elm_s, pair, a);

    __syncthreads();   // stage buffers dead; reuse as reduction staging

    float* accs = (float*)buf;   // 8 * THREADS floats = 24576 B (fits in buf)
    #pragma unroll
    for (int b = 0; b < 8; b++)
        accs[b * THREADS + tid] = a[b];
    __syncthreads();

    // Reduce: first 256 threads; thread owns (bin = tid>>5, lane).
    if (tid < 256) {
        int bin = tid >> 5;
        float sum = 0.0f;
        #pragma unroll
        for (int w = 0; w < NWARP; w++)
            sum += accs[bin * THREADS + (w << 5) + lane];
        #pragma unroll
        for (int off = 16; off > 0; off >>= 1)
            sum += __shfl_down_sync(0xFFFFFFFFu, sum, off);
        if (lane == 0)
            atomicAdd(&out[bin], sum);
    }
}

// ---------------------------------------------------------------------------
// Launch
// ---------------------------------------------------------------------------
extern "C" void kernel_launch(void* const* d_in, const int* in_sizes, int n_in,
                              void* d_out, int out_size)
{
    const int*   elm    = (const int*)  d_in[0];
    const int*   edge_n = (const int*)  d_in[1];
    const int*   edge_i = (const int*)  d_in[2];
    const int*   edge_j = (const int*)  d_in[3];
    const float* sod    = (const float*)d_in[4];
    const float* k      = (const float*)d_in[5];
    const float* radius = (const float*)d_in[6];
    float* out = (float*)d_out;

    int E    = in_sizes[1];
    int nvec = E >> 2;

    cudaFuncSetAttribute(close_penalty_kernel,
                         cudaFuncAttributeMaxDynamicSharedMemorySize, SMEM_TOTAL);

    prep_kernel<<<(ELM_BYTES + 255) / 256, 256>>>(elm, out);

    int grid = GRID_MAIN;
    int nblk = (nvec + THREADS - 1) / THREADS;
    if (nblk < grid) grid = nblk > 0 ? nblk : 1;

    close_penalty_kernel<<<grid, THREADS, SMEM_TOTAL>>>(
        (const int4*)edge_n, (const int4*)edge_i, (const int4*)edge_j,
        (const float4*)sod,
        edge_n, edge_i, edge_j, sod,
        k, radius,
        out, nvec, E);
}